// round 16
// baseline (speedup 1.0000x reference)
#include <cuda_runtime.h>
#include <cuda_fp16.h>
#include <cstdint>

// ---------------------------------------------------------------------------
// StableGATModel: 2-layer GAT (heads=2, hid=64) + linear head.
// R15 -> R16:
//  * GEMM register double-buffering: next chunk's LDGs issued before the mma
//    block, STS deferred to next iteration -> DRAM latency hidden under mma.
//  * activations g_x stored fp16 (half2): edge writes half, GEMM2 + k_final
//    read half -> ~100MB less inter-stage traffic.
//  * edge loop unrolled 4x for deeper gather MLP.
// GEMMs: tf32 mma.sync m16n8k8 (baseline PTX), cvt.rna staging, 128x128 tile.
// Edge: fused single-pass softmax+aggregate (gather, no float atomics).
// ---------------------------------------------------------------------------

constexpr int NN = 100000;
constexpr int NE = 1600000;
constexpr int NB_SCAN = (NN + 1023) / 1024;   // 98

__device__ __half2 g_hh[(size_t)NN * 64];  // GEMM output h, fp16 [node][128]
__device__ __half2 g_x[(size_t)NN * 64];   // activations, fp16 [node][128]
__device__ float4  g_elr[NN];              // {el0, el1, er0, er1}
__device__ int     g_rowstart[NN + 1];
__device__ int     g_cursor[NN];
__device__ int     g_csrc[NE];
__device__ int     g_bsum[128];
__device__ int     g_boff[128];

// ----------------------------- PTX helpers ---------------------------------

__device__ __forceinline__ uint32_t cvt_tf32(float v) {
    uint32_t r; asm("cvt.rna.tf32.f32 %0, %1;" : "=r"(r) : "f"(v)); return r;
}

__device__ __forceinline__ void mma_tf32(float* c, const uint32_t* a,
                                         uint32_t b0, uint32_t b1) {
    asm volatile(
        "mma.sync.aligned.m16n8k8.row.col.f32.tf32.tf32.f32 "
        "{%0,%1,%2,%3}, {%4,%5,%6,%7}, {%8,%9}, {%0,%1,%2,%3};"
        : "+f"(c[0]), "+f"(c[1]), "+f"(c[2]), "+f"(c[3])
        : "r"(a[0]), "r"(a[1]), "r"(a[2]), "r"(a[3]), "r"(b0), "r"(b1));
}

// ------------------------------- CSR build --------------------------------

__global__ void k_hist(const int* __restrict__ dst, int* __restrict__ deg, int e) {
    int i = blockIdx.x * blockDim.x + threadIdx.x;
    if (i < e) atomicAdd(&deg[dst[i]], 1);
}

__global__ void k_scan1(const int* __restrict__ deg, int* __restrict__ incl,
                        int* __restrict__ bsum, int n) {
    __shared__ int sm[1024];
    int t = threadIdx.x;
    int i = blockIdx.x * 1024 + t;
    sm[t] = (i < n) ? deg[i] : 0;
    __syncthreads();
#pragma unroll
    for (int off = 1; off < 1024; off <<= 1) {
        int u = (t >= off) ? sm[t - off] : 0;
        __syncthreads();
        sm[t] += u;
        __syncthreads();
    }
    if (i < n) incl[i] = sm[t];
    if (t == 1023) bsum[blockIdx.x] = sm[1023];
}

__global__ void k_scan2(const int* __restrict__ bsum, int* __restrict__ boff,
                        int nb, int* __restrict__ rowstart) {
    if (threadIdx.x == 0) {
        rowstart[0] = 0;
        int run = 0;
        for (int b = 0; b < nb; ++b) { boff[b] = run; run += bsum[b]; }
    }
}

__global__ void k_scan3(int* __restrict__ incl, const int* __restrict__ boff, int n) {
    int i = blockIdx.x * 1024 + threadIdx.x;
    if (i < n) incl[i] += boff[blockIdx.x];
}

__global__ void k_scatter(const int* __restrict__ src, const int* __restrict__ dst,
                          int* __restrict__ cursor, int* __restrict__ csrc, int e) {
    int i = blockIdx.x * blockDim.x + threadIdx.x;
    if (i < e) {
        int slot = atomicAdd(&cursor[dst[i]], 1);
        csrc[slot] = src[i];
    }
}

// ------------------- tf32 mma.sync GEMM + fused elr epilogue ----------------
// C[128 x 128] = A[128 x K] @ W[K x 128].  8 warps: (wm 0..3, wn 0..1),
// warp tile 32 rows x 64 cols.  Register double-buffered staging.
// AHALF: A operand is fp16 (half2) activations.

template <int K, bool AHALF>
__global__ __launch_bounds__(256)
void k_gemm_mma(const void* __restrict__ Av, const float* __restrict__ W,
                const float* __restrict__ al, const float* __restrict__ ar,
                __half2* __restrict__ H, float4* __restrict__ elr, int n)
{
    __shared__ float As[128][36];   // [row][k]
    __shared__ float Ws[32][136];   // [k][n]

    const int tid  = threadIdx.x;
    const int w    = tid >> 5;
    const int lane = tid & 31;
    const int wm   = w >> 1;        // 0..3
    const int wn   = w & 1;         // 0..1 (== head)
    const int gid  = lane >> 2;     // 0..7
    const int t4   = lane & 3;      // 0..3
    const int brow = blockIdx.x * 128;

    float acc[2][8][4];
#pragma unroll
    for (int mt = 0; mt < 2; ++mt)
#pragma unroll
        for (int nt = 0; nt < 8; ++nt)
#pragma unroll
            for (int i = 0; i < 4; ++i) acc[mt][nt][i] = 0.f;

    float4 pfa[4];     // fp32 A prefetch
    uint4  pfah[2];    // fp16 A prefetch
    float4 pfb[4];     // W prefetch

    auto load_chunk = [&](int k0) {
        if (!AHALF) {
            const float* A = (const float*)Av;
#pragma unroll
            for (int it = 0; it < 4; ++it) {
                int idx = tid + it * 256;
                int row = idx >> 3;
                int q   = (idx & 7) * 4;
                pfa[it] = (brow + row < n)
                    ? *(const float4*)&A[(size_t)(brow + row) * K + k0 + q]
                    : make_float4(0.f, 0.f, 0.f, 0.f);
            }
        } else {
            const __half2* A = (const __half2*)Av;
#pragma unroll
            for (int it = 0; it < 2; ++it) {
                int idx = tid + it * 256;          // 0..511
                int row = idx >> 2;                // 0..127
                int q4  = (idx & 3) * 4;           // half2 offset: 0,4,8,12
                pfah[it] = (brow + row < n)
                    ? *(const uint4*)(A + (size_t)(brow + row) * 64 + (k0 >> 1) + q4)
                    : make_uint4(0u, 0u, 0u, 0u);
            }
        }
#pragma unroll
        for (int it = 0; it < 4; ++it) {
            int idx = tid + it * 256;
            int kk = idx >> 5;
            int nn = (idx & 31) * 4;
            pfb[it] = *(const float4*)&W[(size_t)(k0 + kk) * 128 + nn];
        }
    };

    auto store_chunk = [&]() {
        if (!AHALF) {
#pragma unroll
            for (int it = 0; it < 4; ++it) {
                int idx = tid + it * 256;
                int row = idx >> 3;
                int q   = (idx & 7) * 4;
                uint4 t;
                t.x = cvt_tf32(pfa[it].x); t.y = cvt_tf32(pfa[it].y);
                t.z = cvt_tf32(pfa[it].z); t.w = cvt_tf32(pfa[it].w);
                *(uint4*)&As[row][q] = t;
            }
        } else {
#pragma unroll
            for (int it = 0; it < 2; ++it) {
                int idx = tid + it * 256;
                int row = idx >> 2;
                int q   = (idx & 3) * 8;           // float col 0,8,16,24
                float2 f0 = __half22float2(*(__half2*)&pfah[it].x);
                float2 f1 = __half22float2(*(__half2*)&pfah[it].y);
                float2 f2 = __half22float2(*(__half2*)&pfah[it].z);
                float2 f3 = __half22float2(*(__half2*)&pfah[it].w);
                uint4 t0, t1;
                t0.x = cvt_tf32(f0.x); t0.y = cvt_tf32(f0.y);
                t0.z = cvt_tf32(f1.x); t0.w = cvt_tf32(f1.y);
                t1.x = cvt_tf32(f2.x); t1.y = cvt_tf32(f2.y);
                t1.z = cvt_tf32(f3.x); t1.w = cvt_tf32(f3.y);
                *(uint4*)&As[row][q]     = t0;
                *(uint4*)&As[row][q + 4] = t1;
            }
        }
#pragma unroll
        for (int it = 0; it < 4; ++it) {
            int idx = tid + it * 256;
            int kk = idx >> 5;
            int nn = (idx & 31) * 4;
            uint4 t;
            t.x = cvt_tf32(pfb[it].x); t.y = cvt_tf32(pfb[it].y);
            t.z = cvt_tf32(pfb[it].z); t.w = cvt_tf32(pfb[it].w);
            *(uint4*)&Ws[kk][nn] = t;
        }
    };

    constexpr int NCHUNK = K / 32;
    load_chunk(0);
#pragma unroll
    for (int c = 0; c < NCHUNK; ++c) {
        if (c > 0) __syncthreads();       // compute(c-1) done -> smem free
        store_chunk();
        __syncthreads();
        if (c + 1 < NCHUNK) load_chunk((c + 1) * 32);   // overlap with mma

#pragma unroll
        for (int ks = 0; ks < 4; ++ks) {
            const int kb = ks * 8;
            uint32_t af[2][4];
#pragma unroll
            for (int mt = 0; mt < 2; ++mt) {
                int r0 = wm * 32 + mt * 16 + gid;
                af[mt][0] = __float_as_uint(As[r0    ][kb + t4    ]);
                af[mt][1] = __float_as_uint(As[r0 + 8][kb + t4    ]);
                af[mt][2] = __float_as_uint(As[r0    ][kb + t4 + 4]);
                af[mt][3] = __float_as_uint(As[r0 + 8][kb + t4 + 4]);
            }
#pragma unroll
            for (int nt = 0; nt < 8; ++nt) {
                int cb = wn * 64 + nt * 8 + gid;
                uint32_t b0 = __float_as_uint(Ws[kb + t4    ][cb]);
                uint32_t b1 = __float_as_uint(Ws[kb + t4 + 4][cb]);
                mma_tf32(acc[0][nt], af[0], b0, b1);
                mma_tf32(acc[1][nt], af[1], b0, b1);
            }
        }
    }

    // ---- epilogue: store h (fp16) + fused el/er dots (fp32) ----
    float elp[2][2] = {{0.f, 0.f}, {0.f, 0.f}};
    float erp[2][2] = {{0.f, 0.f}, {0.f, 0.f}};
#pragma unroll
    for (int mt = 0; mt < 2; ++mt) {
        int r0 = brow + wm * 32 + mt * 16 + gid;
#pragma unroll
        for (int nt = 0; nt < 8; ++nt) {
            int col = wn * 64 + nt * 8 + t4 * 2;
            float a0 = al[col], a1 = al[col + 1];
            float r0v = ar[col], r1v = ar[col + 1];
            elp[mt][0] += acc[mt][nt][0] * a0  + acc[mt][nt][1] * a1;
            erp[mt][0] += acc[mt][nt][0] * r0v + acc[mt][nt][1] * r1v;
            elp[mt][1] += acc[mt][nt][2] * a0  + acc[mt][nt][3] * a1;
            erp[mt][1] += acc[mt][nt][2] * r0v + acc[mt][nt][3] * r1v;
            if (r0 < n)
                H[(size_t)r0 * 64 + (col >> 1)] =
                    __floats2half2_rn(acc[mt][nt][0], acc[mt][nt][1]);
            if (r0 + 8 < n)
                H[(size_t)(r0 + 8) * 64 + (col >> 1)] =
                    __floats2half2_rn(acc[mt][nt][2], acc[mt][nt][3]);
        }
    }
#pragma unroll
    for (int mt = 0; mt < 2; ++mt)
#pragma unroll
        for (int h = 0; h < 2; ++h) {
            float e = elp[mt][h], r = erp[mt][h];
            e += __shfl_xor_sync(0xffffffffu, e, 1);
            e += __shfl_xor_sync(0xffffffffu, e, 2);
            r += __shfl_xor_sync(0xffffffffu, r, 1);
            r += __shfl_xor_sync(0xffffffffu, r, 2);
            elp[mt][h] = e; erp[mt][h] = r;
        }
    if (t4 == 0) {
#pragma unroll
        for (int mt = 0; mt < 2; ++mt)
#pragma unroll
            for (int h = 0; h < 2; ++h) {
                int row = brow + wm * 32 + mt * 16 + h * 8 + gid;
                if (row < n) {
                    float* e = (float*)&elr[row];
                    e[wn]     = elp[mt][h];
                    e[2 + wn] = erp[mt][h];
                }
            }
    }
}

// --------------- fused single-pass softmax + aggregation + ELU --------------
// Warp per dst node; out = (sum p_j h_j)/(sum p_j + 1e-9) + b, then ELU.
// Output written as fp16 (half2). Unroll 4 for gather MLP.

__global__ __launch_bounds__(256)
void k_edge(const __half2* __restrict__ h, const int* __restrict__ rowstart,
            const int* __restrict__ csrc, const float4* __restrict__ elr,
            const float* __restrict__ bias, __half2* __restrict__ out, int n) {
    int w = (blockIdx.x * blockDim.x + threadIdx.x) >> 5;
    int lane = threadIdx.x & 31;
    if (w >= n) return;
    int st = rowstart[w], en = rowstart[w + 1];
    float4 me = elr[w];
    const int head = lane >> 4;
    const float er = head ? me.w : me.z;
    const float2* el2 = (const float2*)elr;
    const uint2* hb = (const uint2*)h;

    float s = 0.f;
    float4 acc = make_float4(0.f, 0.f, 0.f, 0.f);

    int j = st;
    for (; j + 3 < en; j += 4) {
        int s0 = csrc[j], s1 = csrc[j + 1], s2 = csrc[j + 2], s3 = csrc[j + 3];
        float2 ev0 = el2[(size_t)s0 * 2];
        float2 ev1 = el2[(size_t)s1 * 2];
        float2 ev2 = el2[(size_t)s2 * 2];
        float2 ev3 = el2[(size_t)s3 * 2];
        uint2 hv0 = hb[(size_t)s0 * 32 + lane];
        uint2 hv1 = hb[(size_t)s1 * 32 + lane];
        uint2 hv2 = hb[(size_t)s2 * 32 + lane];
        uint2 hv3 = hb[(size_t)s3 * 32 + lane];
        float e0 = (head ? ev0.y : ev0.x) + er;
        float e1 = (head ? ev1.y : ev1.x) + er;
        float e2 = (head ? ev2.y : ev2.x) + er;
        float e3 = (head ? ev3.y : ev3.x) + er;
        e0 = (e0 > 0.f) ? e0 : 0.2f * e0;
        e1 = (e1 > 0.f) ? e1 : 0.2f * e1;
        e2 = (e2 > 0.f) ? e2 : 0.2f * e2;
        e3 = (e3 > 0.f) ? e3 : 0.2f * e3;
        float p0 = __expf(e0), p1 = __expf(e1);
        float p2 = __expf(e2), p3 = __expf(e3);
        s += (p0 + p1) + (p2 + p3);
        float2 a01 = __half22float2(*(__half2*)&hv0.x);
        float2 a23 = __half22float2(*(__half2*)&hv0.y);
        float2 b01 = __half22float2(*(__half2*)&hv1.x);
        float2 b23 = __half22float2(*(__half2*)&hv1.y);
        float2 c01 = __half22float2(*(__half2*)&hv2.x);
        float2 c23 = __half22float2(*(__half2*)&hv2.y);
        float2 d01 = __half22float2(*(__half2*)&hv3.x);
        float2 d23 = __half22float2(*(__half2*)&hv3.y);
        acc.x += p0 * a01.x + p1 * b01.x + p2 * c01.x + p3 * d01.x;
        acc.y += p0 * a01.y + p1 * b01.y + p2 * c01.y + p3 * d01.y;
        acc.z += p0 * a23.x + p1 * b23.x + p2 * c23.x + p3 * d23.x;
        acc.w += p0 * a23.y + p1 * b23.y + p2 * c23.y + p3 * d23.y;
    }
    for (; j < en; ++j) {
        int s0 = csrc[j];
        float2 ev0 = el2[(size_t)s0 * 2];
        uint2 hv0 = hb[(size_t)s0 * 32 + lane];
        float e0 = (head ? ev0.y : ev0.x) + er;
        e0 = (e0 > 0.f) ? e0 : 0.2f * e0;
        float p0 = __expf(e0);
        s += p0;
        float2 a01 = __half22float2(*(__half2*)&hv0.x);
        float2 a23 = __half22float2(*(__half2*)&hv0.y);
        acc.x += p0 * a01.x; acc.y += p0 * a01.y;
        acc.z += p0 * a23.x; acc.w += p0 * a23.y;
    }

    float inv = 1.f / (s + 1e-9f);
    float4 bv = *(const float4*)&bias[lane * 4];
    acc.x = acc.x * inv + bv.x;
    acc.y = acc.y * inv + bv.y;
    acc.z = acc.z * inv + bv.z;
    acc.w = acc.w * inv + bv.w;
    acc.x = (acc.x > 0.f) ? acc.x : expm1f(acc.x);
    acc.y = (acc.y > 0.f) ? acc.y : expm1f(acc.y);
    acc.z = (acc.z > 0.f) ? acc.z : expm1f(acc.z);
    acc.w = (acc.w > 0.f) ? acc.w : expm1f(acc.w);
    __half2 h01 = __floats2half2_rn(acc.x, acc.y);
    __half2 h23 = __floats2half2_rn(acc.z, acc.w);
    uint2 pk = make_uint2(*(uint32_t*)&h01, *(uint32_t*)&h23);
    *(uint2*)&out[(size_t)w * 64 + lane * 2] = pk;
}

// ------------------------------- final linear -------------------------------
// [N,128] fp16 @ [128,16] + bl. 16 nodes/block, 256 threads.

__global__ __launch_bounds__(256)
void k_final(const __half2* __restrict__ x, const float* __restrict__ Wl,
             const float* __restrict__ bl, float* __restrict__ y, int n) {
    __shared__ float Ws[128][17];
    __shared__ float xs[16][128];
    int tid = threadIdx.x;
    for (int i = tid; i < 2048; i += 256)
        Ws[i >> 4][i & 15] = Wl[i];
    int base = blockIdx.x * 16;
    {
        int nd = tid >> 4;          // 0..15
        int part = tid & 15;        // 0..15, 8 halfs each
        int g = base + nd;
        uint4 v = make_uint4(0u, 0u, 0u, 0u);
        if (g < n) v = *(const uint4*)(x + (size_t)g * 64 + part * 4);
        float2 f0 = __half22float2(*(__half2*)&v.x);
        float2 f1 = __half22float2(*(__half2*)&v.y);
        float2 f2 = __half22float2(*(__half2*)&v.z);
        float2 f3 = __half22float2(*(__half2*)&v.w);
        float* xr = &xs[nd][part * 8];
        xr[0] = f0.x; xr[1] = f0.y; xr[2] = f1.x; xr[3] = f1.y;
        xr[4] = f2.x; xr[5] = f2.y; xr[6] = f3.x; xr[7] = f3.y;
    }
    __syncthreads();
    int nd = tid >> 4;
    int c  = tid & 15;
    float acc = bl[c];
#pragma unroll 16
    for (int k = 0; k < 128; ++k)
        acc += xs[nd][k] * Ws[k][c];
    int g = base + nd;
    if (g < n) y[(size_t)g * 16 + c] = acc;
}

// --------------------------------- launch ----------------------------------

extern "C" void kernel_launch(void* const* d_in, const int* in_sizes, int n_in,
                              void* d_out, int out_size) {
    const float* features = (const float*)d_in[0];
    const int*   src      = (const int*)  d_in[1];
    const int*   dst      = (const int*)  d_in[2];
    const float* W1  = (const float*)d_in[3];
    const float* al1 = (const float*)d_in[4];
    const float* ar1 = (const float*)d_in[5];
    const float* b1  = (const float*)d_in[6];
    const float* W2  = (const float*)d_in[7];
    const float* al2 = (const float*)d_in[8];
    const float* ar2 = (const float*)d_in[9];
    const float* b2  = (const float*)d_in[10];
    const float* Wl  = (const float*)d_in[11];
    const float* bl  = (const float*)d_in[12];
    float* out = (float*)d_out;

    void *p_hh, *p_x, *p_elr, *p_rs, *p_cur, *p_csrc, *p_bsum, *p_boff;
    cudaGetSymbolAddress(&p_hh,   g_hh);
    cudaGetSymbolAddress(&p_x,    g_x);
    cudaGetSymbolAddress(&p_elr,  g_elr);
    cudaGetSymbolAddress(&p_rs,   g_rowstart);
    cudaGetSymbolAddress(&p_cur,  g_cursor);
    cudaGetSymbolAddress(&p_csrc, g_csrc);
    cudaGetSymbolAddress(&p_bsum, g_bsum);
    cudaGetSymbolAddress(&p_boff, g_boff);

    __half2* hh   = (__half2*)p_hh;
    __half2* xh   = (__half2*)p_x;
    float4*  elr  = (float4*)p_elr;
    int*     rs   = (int*)p_rs;
    int*     cur  = (int*)p_cur;
    int*     csrc = (int*)p_csrc;
    int*     bsum = (int*)p_bsum;
    int*     boff = (int*)p_boff;

    const int EB  = (NE + 255) / 256;         // 6250
    const int WB  = (NN * 32 + 255) / 256;    // 12500 (warp-per-node)
    const int FB  = (NN + 15) / 16;           // 6250
    const int GTC = (NN + 127) / 128;         // 782

    // ---- CSR build (by dst) ----
    cudaMemsetAsync(cur, 0, NN * sizeof(int));
    k_hist<<<EB, 256>>>(dst, cur, NE);
    k_scan1<<<NB_SCAN, 1024>>>(cur, rs + 1, bsum, NN);
    k_scan2<<<1, 32>>>(bsum, boff, NB_SCAN, rs);
    k_scan3<<<NB_SCAN, 1024>>>(rs + 1, boff, NN);
    cudaMemcpyAsync(cur, rs, NN * sizeof(int), cudaMemcpyDeviceToDevice);
    k_scatter<<<EB, 256>>>(src, dst, cur, csrc, NE);

    // ---- Layer 1 ----
    k_gemm_mma<256, false><<<GTC, 256>>>(features, W1, al1, ar1, hh, elr, NN);
    k_edge<<<WB, 256>>>(hh, rs, csrc, elr, b1, xh, NN);

    // ---- Layer 2 ----
    k_gemm_mma<128, true><<<GTC, 256>>>(xh, W2, al2, ar2, hh, elr, NN);
    k_edge<<<WB, 256>>>(hh, rs, csrc, elr, b2, xh, NN);

    // ---- Output head ----
    k_final<<<FB, 256>>>(xh, Wl, bl, out, NN);
}